// round 13
// baseline (speedup 1.0000x reference)
#include <cuda_runtime.h>
#include <cuda_fp16.h>
#include <mma.h>
#include <math.h>

using namespace nvcuda;

#define Bz    8
#define Nn    2048
#define INC   256
#define OUTC  128
#define EDG   65536
#define ROWS  (Bz*Nn)          // 16384
#define CAPD  128              // per-dst CSR capacity (Poisson(32): P(>128)~0)
#define BN_EPS 1e-5f

// ---------------- scratch (static device globals; no runtime alloc) --------
__device__ __half d_Wg16[INC*OUTC];       // mean-over-heads weight, fp16 [256][128]
__device__ float d_Wsd[INC*8];            // [256][8]
__device__ __half d_g16[ROWS*OUTC];       // g, NODE-MAJOR: [n][b][c] fp16 (4 MB)
__device__ float4 d_ssrc[ROWS];           // NODE-MAJOR: [n][b]
__device__ float4 d_sdst[ROWS];           // NODE-MAJOR: [n][b]
__device__ unsigned d_bitmap[(Nn*Nn)/32]; // 512 KB dedup bitmap
__device__ int d_counts[Nn];              // per-dst degree (append cursor)
__device__ int d_colp[Nn*CAPD];           // padded CSR: [dst][CAPD]
__device__ float d_ssum[OUTC];
__device__ float d_ssumsq[OUTC];
__device__ int d_is64;

// ---------------- f32x2 packed helpers (Blackwell) ---------------------------
__device__ __forceinline__ unsigned long long pack2f(float2 v) {
    unsigned long long r;
    asm("mov.b64 %0, {%1, %2};" : "=l"(r) : "f"(v.x), "f"(v.y));
    return r;
}
__device__ __forceinline__ unsigned long long pack2s(float lo, float hi) {
    unsigned long long r;
    asm("mov.b64 %0, {%1, %2};" : "=l"(r) : "f"(lo), "f"(hi));
    return r;
}
__device__ __forceinline__ unsigned long long fma2(unsigned long long a,
                                                   unsigned long long b,
                                                   unsigned long long c) {
    unsigned long long d;
    asm("fma.rn.f32x2 %0, %1, %2, %3;" : "=l"(d) : "l"(a), "l"(b), "l"(c));
    return d;
}
__device__ __forceinline__ float2 unpack2(unsigned long long v) {
    float lo, hi;
    asm("mov.b64 {%0, %1}, %2;" : "=f"(lo), "=f"(hi) : "l"(v));
    return make_float2(lo, hi);
}

// ---------------- reset + edge dtype sniff ----------------------------------
__global__ void k_reset(const unsigned* __restrict__ ei32) {
    int i = blockIdx.x*blockDim.x + threadIdx.x;     // 32768 threads
    uint4* bm4 = (uint4*)d_bitmap;
    bm4[i] = make_uint4(0u,0u,0u,0u);                // 512 KB
    if (i < Nn)  d_counts[i] = 0;
    if (i < OUTC){ d_ssum[i] = 0.f; d_ssumsq[i] = 0.f; }
    if (i == 0) {
        int is64 = 1;
        #pragma unroll 1
        for (int t = 1; t < 128; t += 2)
            if (ei32[t] != 0u) { is64 = 0; break; }
        d_is64 = is64;
    }
}

__device__ __forceinline__ int edge_at(const void* ei, int idx) {
    if (d_is64) return (int)((const long long*)ei)[idx];
    return ((const int*)ei)[idx];
}

// ---------------- dedup + direct padded-CSR append (2 edges/thread) ----------
__global__ void k_dedup(const void* __restrict__ ei) {
    int e0 = (blockIdx.x*blockDim.x + threadIdx.x) * 2;
    if (e0 >= EDG) return;
    int s0 = edge_at(ei, e0),     s1 = edge_at(ei, e0+1);
    int d0 = edge_at(ei, EDG+e0), d1 = edge_at(ei, EDG+e0+1);
    int ss[2] = {s0, s1};
    int dd[2] = {d0, d1};
    #pragma unroll
    for (int i = 0; i < 2; i++) {
        unsigned key = (unsigned)dd[i]*(unsigned)Nn + (unsigned)ss[i];
        unsigned mask = 1u << (key & 31);
        unsigned old = atomicOr(&d_bitmap[key >> 5], mask);
        if (!(old & mask)) {
            int pos = atomicAdd(&d_counts[dd[i]], 1);
            if (pos < CAPD) d_colp[dd[i]*CAPD + pos] = ss[i];
        }
    }
}

// ---------------- fold W,a into Wg16 / Wsd -----------------------------------
__global__ void k_weights(const float* __restrict__ W, const float* __restrict__ a) {
    int k = blockIdx.x;          // 0..255
    int c = threadIdx.x;         // 0..127
    int lane = c & 31, wid = c >> 5;
    __shared__ float part[4][8];
    float w0 = W[k*512 +       c];
    float w1 = W[k*512 + 128 + c];
    float w2 = W[k*512 + 256 + c];
    float w3 = W[k*512 + 384 + c];
    d_Wg16[k*128 + c] = __float2half(0.25f*(w0+w1+w2+w3));
    float as = a[c], ad = a[128+c];
    float vals[8] = {w0*as, w1*as, w2*as, w3*as, w0*ad, w1*ad, w2*ad, w3*ad};
    #pragma unroll
    for (int j = 0; j < 8; j++) {
        float v = vals[j];
        #pragma unroll
        for (int off = 16; off; off >>= 1) v += __shfl_xor_sync(0xffffffff, v, off);
        if (lane == 0) part[wid][j] = v;
    }
    __syncthreads();
    if (c < 8) d_Wsd[k*8 + c] = part[0][c] + part[1][c] + part[2][c] + part[3][c];
}

// ---------------- fused: g = x @ Wg via fp16 HMMA  AND  scores ---------------
// 32x128 tile, 128 threads = 4 warps (2 row-groups x 2 col-groups).
// grid 512 -> ~3.5 blocks/SM in one balanced wave.
__global__ void __launch_bounds__(128) k_gemm_g(const float* __restrict__ x) {
    __shared__ union SM {
        struct {
            __half xa[32][40];     // x tile [row][k] fp16, padded (2.5 KB)
            __half ws[32][136];    // W tile [k][col] fp16, padded (8.7 KB)
            float  sWs[256];       // Wsd tile [k][8] fp32
            float  spart[64][4];   // upper-half score partials
        } m;
        float stage[32][128];      // fp32 output staging (16 KB)
    } sm;

    int block_row = blockIdx.x * 32;
    int tid  = threadIdx.x;
    int wid  = tid >> 5;                 // 0..3
    int wr   = (wid >> 1) * 16;          // warp row offset
    int wc   = (wid & 1) * 64;           // warp col offset
    int srow = (tid & 63) >> 1;          // score row 0..31
    int sq   = (tid & 1) * 4;            // score quad: 0=src, 4=dst
    int kh   = (tid >> 6) * 16;          // score k-half: 0 or 16

    wmma::fragment<wmma::accumulator, 16, 16, 16, float> acc[4];
    #pragma unroll
    for (int c = 0; c < 4; c++) wmma::fill_fragment(acc[c], 0.f);
    float accs0 = 0.f, accs1 = 0.f, accs2 = 0.f, accs3 = 0.f;

    for (int kt = 0; kt < INC; kt += 32) {
        // x tile: 32 rows x 32 k; fp32 load -> fp16 store (256 float4, 2/thread)
        #pragma unroll
        for (int i = 0; i < 2; i++) {
            int f = i*128 + tid;              // 0..255
            int row = f >> 3;
            int kq  = f & 7;
            float4 v = *(const float4*)(x + (size_t)(block_row+row)*INC + kt + kq*4);
            __half2 h0 = __floats2half2_rn(v.x, v.y);
            __half2 h1 = __floats2half2_rn(v.z, v.w);
            uint2 u; u.x = *(unsigned*)&h0; u.y = *(unsigned*)&h1;
            *(uint2*)&sm.m.xa[row][kq*4] = u;
        }
        // W tile: 32 k x 128 cols fp16 (512 uint4 of 8 halves, 4/thread)
        #pragma unroll
        for (int i = 0; i < 4; i++) {
            int f = i*128 + tid;
            int k  = f >> 4;
            int c8 = (f & 15) * 8;
            *(uint4*)&sm.m.ws[k][c8] = *(const uint4*)&d_Wg16[(kt+k)*OUTC + c8];
        }
        sm.m.sWs[tid]       = d_Wsd[kt*8 + tid];
        sm.m.sWs[tid + 128] = d_Wsd[kt*8 + tid + 128];
        __syncthreads();

        // tensor-core mainloop: 2 k-steps of 16
        #pragma unroll
        for (int ks = 0; ks < 32; ks += 16) {
            wmma::fragment<wmma::matrix_a, 16, 16, 16, __half, wmma::row_major> af;
            wmma::load_matrix_sync(af, &sm.m.xa[wr][ks], 40);
            #pragma unroll
            for (int c = 0; c < 4; c++) {
                wmma::fragment<wmma::matrix_b, 16, 16, 16, __half, wmma::row_major> bf;
                wmma::load_matrix_sync(bf, &sm.m.ws[ks][wc + c*16], 136);
                wmma::mma_sync(acc[c], af, bf, acc[c]);
            }
        }

        // fused score accumulation: 16 k per thread (k-half each)
        #pragma unroll
        for (int k = 0; k < 16; k++) {
            float xvs = __half2float(sm.m.xa[srow][kh + k]);
            float4 wsd = *(const float4*)&sm.m.sWs[(kh + k)*8 + sq];
            accs0 += xvs*wsd.x; accs1 += xvs*wsd.y;
            accs2 += xvs*wsd.z; accs3 += xvs*wsd.w;
        }
        __syncthreads();
    }

    // combine score halves (upper 64 threads -> smem, lower adds)
    if (tid >= 64 && tid < 128) {
        sm.m.spart[tid-64][0] = accs0; sm.m.spart[tid-64][1] = accs1;
        sm.m.spart[tid-64][2] = accs2; sm.m.spart[tid-64][3] = accs3;
    }
    __syncthreads();
    if (tid < 64) {
        float4 sv = make_float4(accs0 + sm.m.spart[tid][0],
                                accs1 + sm.m.spart[tid][1],
                                accs2 + sm.m.spart[tid][2],
                                accs3 + sm.m.spart[tid][3]);
        int grow = block_row + srow;
        int gb_ = grow >> 11;
        int gn  = grow & (Nn-1);
        if (sq == 0) d_ssrc[gn*8 + gb_] = sv;    // node-major
        else         d_sdst[gn*8 + gb_] = sv;
    }
    __syncthreads();   // spart reads done before stage overwrites the union

    // epilogue: stage fp32 results, then emit fp16 node-major
    #pragma unroll
    for (int c = 0; c < 4; c++)
        wmma::store_matrix_sync(&sm.stage[wr][wc + c*16], acc[c], 128, wmma::mem_row_major);
    __syncthreads();

    int tx = tid & 15;          // 8-col group
    int ty = tid >> 4;          // 0..7
    #pragma unroll
    for (int r = ty; r < 32; r += 8) {
        int row = block_row + r;
        int bb = row >> 11;
        int nn = row & (Nn-1);
        const float* st = &sm.stage[r][tx*8];
        __half2 h0 = __floats2half2_rn(st[0], st[1]);
        __half2 h1 = __floats2half2_rn(st[2], st[3]);
        __half2 h2 = __floats2half2_rn(st[4], st[5]);
        __half2 h3 = __floats2half2_rn(st[6], st[7]);
        uint4 u;
        u.x = *(unsigned*)&h0; u.y = *(unsigned*)&h1;
        u.z = *(unsigned*)&h2; u.w = *(unsigned*)&h3;
        *(uint4*)&d_g16[(size_t)(nn*8 + bb)*OUTC + tx*8] = u;   // node-major
    }
}

__device__ __forceinline__ float edge_val(float4 ss, float4 sd) {
    float v0 = ss.x + sd.x, v1 = ss.y + sd.y, v2 = ss.z + sd.z, v3 = ss.w + sd.w;
    v0 = v0 > 0.f ? v0 : 0.2f*v0;
    v1 = v1 > 0.f ? v1 : 0.2f*v1;
    v2 = v2 > 0.f ? v2 : 0.2f*v2;
    v3 = v3 > 0.f ? v3 : 0.2f*v3;
    return 0.25f*(v0+v1+v2+v3);
}

// ---------------- agg: block/dst, warp/batch; f32x2 FMA, unroll 8 ------------
// No max subtraction: scores bounded, expf exact in fp32, softmax shift-invariant.
__global__ void __launch_bounds__(256) k_agg(float* __restrict__ out) {
    int d    = blockIdx.x;
    int b    = threadIdx.x >> 5;    // warp = batch
    int lane = threadIdx.x & 31;
    int cnt  = min(d_counts[d], CAPD);
    float4* o4 = (float4*)(out + ((size_t)b*Nn + d)*OUTC);

    if (cnt == 0) { o4[lane] = make_float4(0.f,0.f,0.f,0.f); return; }

    __shared__ int   scol[CAPD];
    __shared__ float sp[8][CAPD];
    __shared__ float sb[8][128];
    __shared__ float sb2[8][128];

    if (threadIdx.x < cnt) scol[threadIdx.x] = __ldg(&d_colp[d*CAPD + threadIdx.x]);
    __syncthreads();

    float4 sd = d_sdst[d*8 + b];                 // node-major
    float lsum = 0.f;
    unsigned long long acc01 = 0ULL, acc23 = 0ULL;
    const uint2* gb = (const uint2*)d_g16;       // row (n*8+b) = 32 uint2

    for (int jj = lane; jj < cnt; jj += 32) {
        int s = scol[jj];
        float p = __expf(edge_val(d_ssrc[s*8 + b], sd));
        sp[b][jj] = p;
        lsum += p;
    }
    __syncwarp();
    int jj = 0;
    for (; jj + 8 <= cnt; jj += 8) {
        uint2 u[8];
        float p[8];
        #pragma unroll
        for (int i = 0; i < 8; i++) {
            p[i] = sp[b][jj+i];
            u[i] = __ldg(gb + ((size_t)scol[jj+i]*8 + b)*32 + lane);
        }
        #pragma unroll
        for (int i = 0; i < 8; i++) {
            unsigned long long pd = pack2s(p[i], p[i]);
            float2 f0 = __half22float2(*(__half2*)&u[i].x);
            float2 f1 = __half22float2(*(__half2*)&u[i].y);
            acc01 = fma2(pd, pack2f(f0), acc01);
            acc23 = fma2(pd, pack2f(f1), acc23);
        }
    }
    for (; jj < cnt; jj++) {
        float p = sp[b][jj];
        uint2 u = __ldg(gb + ((size_t)scol[jj]*8 + b)*32 + lane);
        unsigned long long pd = pack2s(p, p);
        float2 f0 = __half22float2(*(__half2*)&u.x);
        float2 f1 = __half22float2(*(__half2*)&u.y);
        acc01 = fma2(pd, pack2f(f0), acc01);
        acc23 = fma2(pd, pack2f(f1), acc23);
    }
    #pragma unroll
    for (int off = 16; off; off >>= 1)
        lsum += __shfl_xor_sync(0xffffffff, lsum, off);
    float inv = 1.f / lsum;
    float2 c01 = unpack2(acc01);
    float2 c23 = unpack2(acc23);
    float a0 = c01.x*inv, a1 = c01.y*inv, a2 = c23.x*inv, a3 = c23.y*inv;
    o4[lane] = make_float4(a0, a1, a2, a3);

    // fused BN partials
    int c0 = lane*4;
    sb [b][c0+0]=a0;    sb [b][c0+1]=a1;    sb [b][c0+2]=a2;    sb [b][c0+3]=a3;
    sb2[b][c0+0]=a0*a0; sb2[b][c0+1]=a1*a1; sb2[b][c0+2]=a2*a2; sb2[b][c0+3]=a3*a3;
    __syncthreads();
    int t = threadIdx.x;
    if (t < 128) {
        float s = 0.f, s2 = 0.f;
        #pragma unroll
        for (int w = 0; w < 8; w++) { s += sb[w][t]; s2 += sb2[w][t]; }
        atomicAdd(&d_ssum[t], s);
        atomicAdd(&d_ssumsq[t], s2);
    }
}

// ---------------- BN apply + ELU (in place, float4) --------------------------
__global__ void k_final(float* __restrict__ out,
                        const float* __restrict__ gamma,
                        const float* __restrict__ beta) {
    int i = blockIdx.x*blockDim.x + threadIdx.x;     // float4 index
    if (i >= ROWS*OUTC/4) return;
    int c0 = (i*4) & (OUTC-1);
    const float inv = 1.f/(float)ROWS;
    float4 v = ((const float4*)out)[i];
    float r[4] = {v.x, v.y, v.z, v.w};
    #pragma unroll
    for (int j = 0; j < 4; j++) {
        int c = c0 + j;
        float mean = d_ssum[c]  * inv;
        float var  = d_ssumsq[c]* inv - mean*mean;
        float y = (r[j] - mean) * rsqrtf(var + BN_EPS) * __ldg(&gamma[c]) + __ldg(&beta[c]);
        r[j] = y > 0.f ? y : expm1f(y);
    }
    ((float4*)out)[i] = make_float4(r[0], r[1], r[2], r[3]);
}

// ---------------- launch: fork-join graph ------------------------------------
extern "C" void kernel_launch(void* const* d_in, const int* in_sizes, int n_in,
                              void* d_out, int out_size) {
    const float* x     = (const float*)d_in[0];
    const void*  ei    = d_in[1];
    const float* W     = (const float*)d_in[2];
    const float* a     = (const float*)d_in[3];
    const float* gamma = (const float*)d_in[4];
    const float* beta  = (const float*)d_in[5];
    float* out = (float*)d_out;

    static cudaStream_t s1 = nullptr;
    static cudaEvent_t  e0 = nullptr, e1 = nullptr;
    if (s1 == nullptr) {
        cudaStreamCreateWithFlags(&s1, cudaStreamNonBlocking);
        cudaEventCreateWithFlags(&e0, cudaEventDisableTiming);
        cudaEventCreateWithFlags(&e1, cudaEventDisableTiming);
    }

    // fork side stream at t=0; submit its kernels first
    cudaEventRecord(e0, 0);
    cudaStreamWaitEvent(s1, e0, 0);
    k_reset  <<<128, 256, 0, s1>>>((const unsigned*)ei);
    k_dedup  <<<EDG/512, 256, 0, s1>>>(ei);
    cudaEventRecord(e1, s1);

    // main stream: weights -> fused fp16 GEMM+scores
    k_weights<<<INC, 128>>>(W, a);
    k_gemm_g <<<ROWS/32, 128>>>(x);

    // join: aggregation (+BN stats) + BN/ELU
    cudaStreamWaitEvent(0, e1, 0);
    k_agg    <<<Nn, 256>>>(out);
    k_final  <<<(ROWS*OUTC/4 + 255)/256, 256>>>(out, gamma, beta);
}

// round 14
// speedup vs baseline: 1.1124x; 1.1124x over previous
#include <cuda_runtime.h>
#include <cuda_fp16.h>
#include <mma.h>
#include <math.h>

using namespace nvcuda;

#define Bz    8
#define Nn    2048
#define INC   256
#define OUTC  128
#define NAUG  144              // 128 g-cols + 8 score cols + 8 zero pad
#define EDG   65536
#define ROWS  (Bz*Nn)          // 16384
#define CAPD  128              // per-dst CSR capacity (Poisson(32): P(>128)~0)
#define BN_EPS 1e-5f

// ---------------- scratch (static device globals; no runtime alloc) --------
__device__ __half d_Waug[INC*NAUG];       // [Wg | Wsd | 0] fp16 [256][144]
__device__ __half d_g16[ROWS*OUTC];       // g, NODE-MAJOR: [n][b][c] fp16 (4 MB)
__device__ float4 d_ssrc[ROWS];           // NODE-MAJOR: [n][b]
__device__ float4 d_sdst[ROWS];           // NODE-MAJOR: [n][b]
__device__ unsigned d_bitmap[(Nn*Nn)/32]; // 512 KB dedup bitmap
__device__ int d_counts[Nn];              // per-dst degree (append cursor)
__device__ int d_colp[Nn*CAPD];           // padded CSR: [dst][CAPD]
__device__ float d_ssum[OUTC];
__device__ float d_ssumsq[OUTC];
__device__ int d_is64;

// ---------------- reset + edge dtype sniff ----------------------------------
__global__ void k_reset(const unsigned* __restrict__ ei32) {
    int i = blockIdx.x*blockDim.x + threadIdx.x;     // 32768 threads
    uint4* bm4 = (uint4*)d_bitmap;
    bm4[i] = make_uint4(0u,0u,0u,0u);                // 512 KB
    if (i < Nn)  d_counts[i] = 0;
    if (i < OUTC){ d_ssum[i] = 0.f; d_ssumsq[i] = 0.f; }
    if (i == 0) {
        int is64 = 1;
        #pragma unroll 1
        for (int t = 1; t < 128; t += 2)
            if (ei32[t] != 0u) { is64 = 0; break; }
        d_is64 = is64;
    }
}

__device__ __forceinline__ int edge_at(const void* ei, int idx) {
    if (d_is64) return (int)((const long long*)ei)[idx];
    return ((const int*)ei)[idx];
}

// ---------------- dedup + direct padded-CSR append (2 edges/thread) ----------
__global__ void k_dedup(const void* __restrict__ ei) {
    int e0 = (blockIdx.x*blockDim.x + threadIdx.x) * 2;
    if (e0 >= EDG) return;
    int s0 = edge_at(ei, e0),     s1 = edge_at(ei, e0+1);
    int d0 = edge_at(ei, EDG+e0), d1 = edge_at(ei, EDG+e0+1);
    int ss[2] = {s0, s1};
    int dd[2] = {d0, d1};
    #pragma unroll
    for (int i = 0; i < 2; i++) {
        unsigned key = (unsigned)dd[i]*(unsigned)Nn + (unsigned)ss[i];
        unsigned mask = 1u << (key & 31);
        unsigned old = atomicOr(&d_bitmap[key >> 5], mask);
        if (!(old & mask)) {
            int pos = atomicAdd(&d_counts[dd[i]], 1);
            if (pos < CAPD) d_colp[dd[i]*CAPD + pos] = ss[i];
        }
    }
}

// ---------------- fold W,a into Waug = [Wg | Wsd | 0] ------------------------
__global__ void k_weights(const float* __restrict__ W, const float* __restrict__ a) {
    int k = blockIdx.x;          // 0..255
    int c = threadIdx.x;         // 0..127
    int lane = c & 31, wid = c >> 5;
    __shared__ float part[4][8];
    float w0 = W[k*512 +       c];
    float w1 = W[k*512 + 128 + c];
    float w2 = W[k*512 + 256 + c];
    float w3 = W[k*512 + 384 + c];
    d_Waug[k*NAUG + c] = __float2half(0.25f*(w0+w1+w2+w3));
    float as = a[c], ad = a[128+c];
    float vals[8] = {w0*as, w1*as, w2*as, w3*as, w0*ad, w1*ad, w2*ad, w3*ad};
    #pragma unroll
    for (int j = 0; j < 8; j++) {
        float v = vals[j];
        #pragma unroll
        for (int off = 16; off; off >>= 1) v += __shfl_xor_sync(0xffffffff, v, off);
        if (lane == 0) part[wid][j] = v;
    }
    __syncthreads();
    if (c < 8)
        d_Waug[k*NAUG + 128 + c] =
            __float2half(part[0][c] + part[1][c] + part[2][c] + part[3][c]);
    else if (c < 16)
        d_Waug[k*NAUG + 128 + c] = __float2half(0.f);
}

// ---------------- fused GEMM: [g | scores] = x @ Waug via fp16 HMMA ----------
// 64x144 tile, 256 threads = 8 warps (4 row-groups x 2 col-groups of 64);
// wc==0 warps also carry the 16-wide score column block (cols 128..143).
__global__ void __launch_bounds__(256) k_gemm_g(const float* __restrict__ x) {
    __shared__ union SM {
        struct {
            __half xa[64][40];     // x tile [row][k] fp16, padded (5.1 KB)
            __half ws[32][152];    // Waug tile [k][col] fp16, padded (9.5 KB)
        } m;
        float stage[64][152];      // fp32 output staging (38.9 KB)
    } sm;

    int block_row = blockIdx.x * 64;
    int tid  = threadIdx.x;
    int wid  = tid >> 5;                 // 0..7
    int wr   = (wid >> 1) * 16;          // warp row offset
    int wc   = (wid & 1) * 64;           // warp col offset

    wmma::fragment<wmma::accumulator, 16, 16, 16, float> acc[4];
    wmma::fragment<wmma::accumulator, 16, 16, 16, float> accS;
    #pragma unroll
    for (int c = 0; c < 4; c++) wmma::fill_fragment(acc[c], 0.f);
    wmma::fill_fragment(accS, 0.f);

    for (int kt = 0; kt < INC; kt += 32) {
        // x tile: 64 rows x 32 k; fp32 load -> fp16 store (512 float4)
        #pragma unroll
        for (int i = 0; i < 2; i++) {
            int f = i*256 + tid;              // 0..511
            int row = f >> 3;
            int kq  = f & 7;
            float4 v = *(const float4*)(x + (size_t)(block_row+row)*INC + kt + kq*4);
            __half2 h0 = __floats2half2_rn(v.x, v.y);
            __half2 h1 = __floats2half2_rn(v.z, v.w);
            uint2 u; u.x = *(unsigned*)&h0; u.y = *(unsigned*)&h1;
            *(uint2*)&sm.m.xa[row][kq*4] = u;
        }
        // Waug tile: 32 k x 144 cols fp16 = 576 uint4 (18 per k-row)
        #pragma unroll
        for (int i = 0; i < 3; i++) {
            int f = i*256 + tid;
            if (f < 576) {
                int k  = f / 18;
                int c8 = (f - k*18) * 8;
                *(uint4*)&sm.m.ws[k][c8] = *(const uint4*)&d_Waug[(kt+k)*NAUG + c8];
            }
        }
        __syncthreads();

        // tensor-core mainloop: 2 k-steps of 16
        #pragma unroll
        for (int ks = 0; ks < 32; ks += 16) {
            wmma::fragment<wmma::matrix_a, 16, 16, 16, __half, wmma::row_major> af;
            wmma::load_matrix_sync(af, &sm.m.xa[wr][ks], 40);
            #pragma unroll
            for (int c = 0; c < 4; c++) {
                wmma::fragment<wmma::matrix_b, 16, 16, 16, __half, wmma::row_major> bf;
                wmma::load_matrix_sync(bf, &sm.m.ws[ks][wc + c*16], 152);
                wmma::mma_sync(acc[c], af, bf, acc[c]);
            }
            if (wc == 0) {
                wmma::fragment<wmma::matrix_b, 16, 16, 16, __half, wmma::row_major> bf;
                wmma::load_matrix_sync(bf, &sm.m.ws[ks][128], 152);
                wmma::mma_sync(accS, af, bf, accS);
            }
        }
        __syncthreads();
    }

    // epilogue: stage fp32 results, then emit fp16 g (node-major) + scores
    #pragma unroll
    for (int c = 0; c < 4; c++)
        wmma::store_matrix_sync(&sm.stage[wr][wc + c*16], acc[c], 152, wmma::mem_row_major);
    if (wc == 0)
        wmma::store_matrix_sync(&sm.stage[wr][128], accS, 152, wmma::mem_row_major);
    __syncthreads();

    int tx = tid & 15;          // 8-col group
    int ty = tid >> 4;          // 0..15
    #pragma unroll
    for (int r = ty; r < 64; r += 16) {
        int row = block_row + r;
        int bb = row >> 11;
        int nn = row & (Nn-1);
        const float* st = &sm.stage[r][tx*8];
        __half2 h0 = __floats2half2_rn(st[0], st[1]);
        __half2 h1 = __floats2half2_rn(st[2], st[3]);
        __half2 h2 = __floats2half2_rn(st[4], st[5]);
        __half2 h3 = __floats2half2_rn(st[6], st[7]);
        uint4 u;
        u.x = *(unsigned*)&h0; u.y = *(unsigned*)&h1;
        u.z = *(unsigned*)&h2; u.w = *(unsigned*)&h3;
        *(uint4*)&d_g16[(size_t)(nn*8 + bb)*OUTC + tx*8] = u;   // node-major
    }

    if (tid < 128) {
        int srow = tid >> 1;             // 0..63
        int sq   = (tid & 1) * 4;        // 0 = src cols, 4 = dst cols
        const float* st = &sm.stage[srow][128 + sq];
        float4 sv = make_float4(st[0], st[1], st[2], st[3]);
        int grow = block_row + srow;
        int gb_ = grow >> 11;
        int gn  = grow & (Nn-1);
        if (sq == 0) d_ssrc[gn*8 + gb_] = sv;    // node-major
        else         d_sdst[gn*8 + gb_] = sv;
    }
}

__device__ __forceinline__ float edge_val(float4 ss, float4 sd) {
    float v0 = ss.x + sd.x, v1 = ss.y + sd.y, v2 = ss.z + sd.z, v3 = ss.w + sd.w;
    v0 = v0 > 0.f ? v0 : 0.2f*v0;
    v1 = v1 > 0.f ? v1 : 0.2f*v1;
    v2 = v2 > 0.f ? v2 : 0.2f*v2;
    v3 = v3 > 0.f ? v3 : 0.2f*v3;
    return 0.25f*(v0+v1+v2+v3);
}

// ---------------- agg: block/dst, warp/batch, single smem stage (round-12) ---
// No max subtraction: scores bounded, expf exact in fp32, softmax shift-invariant.
__global__ void __launch_bounds__(256) k_agg(float* __restrict__ out) {
    int d    = blockIdx.x;
    int b    = threadIdx.x >> 5;    // warp = batch
    int lane = threadIdx.x & 31;
    int cnt  = min(d_counts[d], CAPD);
    float4* o4 = (float4*)(out + ((size_t)b*Nn + d)*OUTC);

    if (cnt == 0) { o4[lane] = make_float4(0.f,0.f,0.f,0.f); return; }

    __shared__ int   scol[CAPD];
    __shared__ float sp[8][CAPD];
    __shared__ float sb[8][128];
    __shared__ float sb2[8][128];

    if (threadIdx.x < cnt) scol[threadIdx.x] = __ldg(&d_colp[d*CAPD + threadIdx.x]);
    __syncthreads();

    float4 sd = d_sdst[d*8 + b];                 // node-major
    float a0=0.f, a1=0.f, a2=0.f, a3=0.f, lsum=0.f;
    const uint2* gb = (const uint2*)d_g16;       // row (n*8+b) = 32 uint2

    for (int jj = lane; jj < cnt; jj += 32) {
        int s = scol[jj];
        float p = __expf(edge_val(d_ssrc[s*8 + b], sd));
        sp[b][jj] = p;
        lsum += p;
    }
    __syncwarp();
    int jj = 0;
    for (; jj + 4 <= cnt; jj += 4) {
        float p0 = sp[b][jj],   p1 = sp[b][jj+1];
        float p2 = sp[b][jj+2], p3 = sp[b][jj+3];
        size_t r0 = (size_t)scol[jj]*8   + b;
        size_t r1 = (size_t)scol[jj+1]*8 + b;
        size_t r2 = (size_t)scol[jj+2]*8 + b;
        size_t r3 = (size_t)scol[jj+3]*8 + b;
        uint2 u0 = __ldg(gb + r0*32 + lane);
        uint2 u1 = __ldg(gb + r1*32 + lane);
        uint2 u2 = __ldg(gb + r2*32 + lane);
        uint2 u3 = __ldg(gb + r3*32 + lane);
        float2 f;
        f = __half22float2(*(__half2*)&u0.x); a0 += p0*f.x; a1 += p0*f.y;
        f = __half22float2(*(__half2*)&u0.y); a2 += p0*f.x; a3 += p0*f.y;
        f = __half22float2(*(__half2*)&u1.x); a0 += p1*f.x; a1 += p1*f.y;
        f = __half22float2(*(__half2*)&u1.y); a2 += p1*f.x; a3 += p1*f.y;
        f = __half22float2(*(__half2*)&u2.x); a0 += p2*f.x; a1 += p2*f.y;
        f = __half22float2(*(__half2*)&u2.y); a2 += p2*f.x; a3 += p2*f.y;
        f = __half22float2(*(__half2*)&u3.x); a0 += p3*f.x; a1 += p3*f.y;
        f = __half22float2(*(__half2*)&u3.y); a2 += p3*f.x; a3 += p3*f.y;
    }
    for (; jj < cnt; jj++) {
        float p = sp[b][jj];
        uint2 u = __ldg(gb + ((size_t)scol[jj]*8 + b)*32 + lane);
        float2 f;
        f = __half22float2(*(__half2*)&u.x); a0 += p*f.x; a1 += p*f.y;
        f = __half22float2(*(__half2*)&u.y); a2 += p*f.x; a3 += p*f.y;
    }
    #pragma unroll
    for (int off = 16; off; off >>= 1)
        lsum += __shfl_xor_sync(0xffffffff, lsum, off);
    float inv = 1.f / lsum;
    a0 *= inv; a1 *= inv; a2 *= inv; a3 *= inv;
    o4[lane] = make_float4(a0, a1, a2, a3);

    // fused BN partials
    int c0 = lane*4;
    sb [b][c0+0]=a0;    sb [b][c0+1]=a1;    sb [b][c0+2]=a2;    sb [b][c0+3]=a3;
    sb2[b][c0+0]=a0*a0; sb2[b][c0+1]=a1*a1; sb2[b][c0+2]=a2*a2; sb2[b][c0+3]=a3*a3;
    __syncthreads();
    int t = threadIdx.x;
    if (t < 128) {
        float s = 0.f, s2 = 0.f;
        #pragma unroll
        for (int w = 0; w < 8; w++) { s += sb[w][t]; s2 += sb2[w][t]; }
        atomicAdd(&d_ssum[t], s);
        atomicAdd(&d_ssumsq[t], s2);
    }
}

// ---------------- BN apply + ELU (in place, float4) --------------------------
__global__ void k_final(float* __restrict__ out,
                        const float* __restrict__ gamma,
                        const float* __restrict__ beta) {
    int i = blockIdx.x*blockDim.x + threadIdx.x;     // float4 index
    if (i >= ROWS*OUTC/4) return;
    int c0 = (i*4) & (OUTC-1);
    const float inv = 1.f/(float)ROWS;
    float4 v = ((const float4*)out)[i];
    float r[4] = {v.x, v.y, v.z, v.w};
    #pragma unroll
    for (int j = 0; j < 4; j++) {
        int c = c0 + j;
        float mean = d_ssum[c]  * inv;
        float var  = d_ssumsq[c]* inv - mean*mean;
        float y = (r[j] - mean) * rsqrtf(var + BN_EPS) * __ldg(&gamma[c]) + __ldg(&beta[c]);
        r[j] = y > 0.f ? y : expm1f(y);
    }
    ((float4*)out)[i] = make_float4(r[0], r[1], r[2], r[3]);
}

// ---------------- launch: fork-join graph ------------------------------------
extern "C" void kernel_launch(void* const* d_in, const int* in_sizes, int n_in,
                              void* d_out, int out_size) {
    const float* x     = (const float*)d_in[0];
    const void*  ei    = d_in[1];
    const float* W     = (const float*)d_in[2];
    const float* a     = (const float*)d_in[3];
    const float* gamma = (const float*)d_in[4];
    const float* beta  = (const float*)d_in[5];
    float* out = (float*)d_out;

    static cudaStream_t s1 = nullptr;
    static cudaEvent_t  e0 = nullptr, e1 = nullptr;
    if (s1 == nullptr) {
        cudaStreamCreateWithFlags(&s1, cudaStreamNonBlocking);
        cudaEventCreateWithFlags(&e0, cudaEventDisableTiming);
        cudaEventCreateWithFlags(&e1, cudaEventDisableTiming);
    }

    // fork side stream at t=0; submit its kernels first
    cudaEventRecord(e0, 0);
    cudaStreamWaitEvent(s1, e0, 0);
    k_reset  <<<128, 256, 0, s1>>>((const unsigned*)ei);
    k_dedup  <<<EDG/512, 256, 0, s1>>>(ei);
    cudaEventRecord(e1, s1);

    // main stream: weights -> fused fp16 GEMM (+tensorized scores)
    k_weights<<<INC, 128>>>(W, a);
    k_gemm_g <<<ROWS/64, 256>>>(x);

    // join: aggregation (+BN stats) + BN/ELU
    cudaStreamWaitEvent(0, e1, 0);
    k_agg    <<<Nn, 256>>>(out);
    k_final  <<<(ROWS*OUTC/4 + 255)/256, 256>>>(out, gamma, beta);
}

// round 15
// speedup vs baseline: 1.1956x; 1.0748x over previous
#include <cuda_runtime.h>
#include <cuda_fp16.h>
#include <mma.h>
#include <math.h>

using namespace nvcuda;

#define Bz    8
#define Nn    2048
#define INC   256
#define OUTC  128
#define NAUG  144              // 128 g-cols + 8 score cols + 8 zero pad
#define EDG   65536
#define ROWS  (Bz*Nn)          // 16384
#define CAPD  128              // per-dst CSR capacity (Poisson(32): P(>128)~0)
#define BN_EPS 1e-5f

// ---------------- scratch (static device globals; no runtime alloc) --------
__device__ __half d_Waug[INC*NAUG];       // [Wg | Wsd | 0] fp16 [256][144]
__device__ __half d_g16[ROWS*OUTC];       // g, NODE-MAJOR: [n][b][c] fp16 (4 MB)
__device__ float4 d_ssrc[ROWS];           // NODE-MAJOR: [n][b]
__device__ float4 d_sdst[ROWS];           // NODE-MAJOR: [n][b]
__device__ unsigned d_bitmap[(Nn*Nn)/32]; // 512 KB dedup bitmap
__device__ int d_counts[Nn];              // per-dst degree (append cursor)
__device__ int d_colp[Nn*CAPD];           // padded CSR: [dst][CAPD]
__device__ float d_ssum[OUTC];
__device__ float d_ssumsq[OUTC];
__device__ int d_is64;

// ---------------- f32x2 packed helpers (Blackwell) ---------------------------
__device__ __forceinline__ unsigned long long pack2f(float2 v) {
    unsigned long long r;
    asm("mov.b64 %0, {%1, %2};" : "=l"(r) : "f"(v.x), "f"(v.y));
    return r;
}
__device__ __forceinline__ unsigned long long pack2s(float lo, float hi) {
    unsigned long long r;
    asm("mov.b64 %0, {%1, %2};" : "=l"(r) : "f"(lo), "f"(hi));
    return r;
}
__device__ __forceinline__ unsigned long long fma2(unsigned long long a,
                                                   unsigned long long b,
                                                   unsigned long long c) {
    unsigned long long d;
    asm("fma.rn.f32x2 %0, %1, %2, %3;" : "=l"(d) : "l"(a), "l"(b), "l"(c));
    return d;
}
__device__ __forceinline__ float2 unpack2(unsigned long long v) {
    float lo, hi;
    asm("mov.b64 {%0, %1}, %2;" : "=f"(lo), "=f"(hi) : "l"(v));
    return make_float2(lo, hi);
}

// ---------------- reset + edge dtype sniff ----------------------------------
__global__ void k_reset(const unsigned* __restrict__ ei32) {
    int i = blockIdx.x*blockDim.x + threadIdx.x;     // 32768 threads
    uint4* bm4 = (uint4*)d_bitmap;
    bm4[i] = make_uint4(0u,0u,0u,0u);                // 512 KB
    if (i < Nn)  d_counts[i] = 0;
    if (i < OUTC){ d_ssum[i] = 0.f; d_ssumsq[i] = 0.f; }
    if (i == 0) {
        int is64 = 1;
        #pragma unroll 1
        for (int t = 1; t < 128; t += 2)
            if (ei32[t] != 0u) { is64 = 0; break; }
        d_is64 = is64;
    }
}

__device__ __forceinline__ int edge_at(const void* ei, int idx) {
    if (d_is64) return (int)((const long long*)ei)[idx];
    return ((const int*)ei)[idx];
}

// ---------------- dedup + direct padded-CSR append (2 edges/thread) ----------
__global__ void k_dedup(const void* __restrict__ ei) {
    int e0 = (blockIdx.x*blockDim.x + threadIdx.x) * 2;
    if (e0 >= EDG) return;
    int s0 = edge_at(ei, e0),     s1 = edge_at(ei, e0+1);
    int d0 = edge_at(ei, EDG+e0), d1 = edge_at(ei, EDG+e0+1);
    int ss[2] = {s0, s1};
    int dd[2] = {d0, d1};
    #pragma unroll
    for (int i = 0; i < 2; i++) {
        unsigned key = (unsigned)dd[i]*(unsigned)Nn + (unsigned)ss[i];
        unsigned mask = 1u << (key & 31);
        unsigned old = atomicOr(&d_bitmap[key >> 5], mask);
        if (!(old & mask)) {
            int pos = atomicAdd(&d_counts[dd[i]], 1);
            if (pos < CAPD) d_colp[dd[i]*CAPD + pos] = ss[i];
        }
    }
}

// ---------------- fold W,a into Waug = [Wg | Wsd | 0] ------------------------
__global__ void k_weights(const float* __restrict__ W, const float* __restrict__ a) {
    int k = blockIdx.x;          // 0..255
    int c = threadIdx.x;         // 0..127
    int lane = c & 31, wid = c >> 5;
    __shared__ float part[4][8];
    float w0 = W[k*512 +       c];
    float w1 = W[k*512 + 128 + c];
    float w2 = W[k*512 + 256 + c];
    float w3 = W[k*512 + 384 + c];
    d_Waug[k*NAUG + c] = __float2half(0.25f*(w0+w1+w2+w3));
    float as = a[c], ad = a[128+c];
    float vals[8] = {w0*as, w1*as, w2*as, w3*as, w0*ad, w1*ad, w2*ad, w3*ad};
    #pragma unroll
    for (int j = 0; j < 8; j++) {
        float v = vals[j];
        #pragma unroll
        for (int off = 16; off; off >>= 1) v += __shfl_xor_sync(0xffffffff, v, off);
        if (lane == 0) part[wid][j] = v;
    }
    __syncthreads();
    if (c < 8)
        d_Waug[k*NAUG + 128 + c] =
            __float2half(part[0][c] + part[1][c] + part[2][c] + part[3][c]);
    else if (c < 16)
        d_Waug[k*NAUG + 128 + c] = __float2half(0.f);
}

// ---------------- fused GEMM: [g | scores] = x @ Waug, double-buffered -------
// 64x144 tile, 256 threads = 8 warps (4 row-groups x 2 col-groups of 64);
// wc==0 warps also carry the 16-wide score column block (cols 128..143).
__global__ void __launch_bounds__(256) k_gemm_g(const float* __restrict__ x) {
    __shared__ union SM {
        struct {
            __half xa[64][40];     // x tile [row][k] fp16, padded
            __half ws[32][152];    // Waug tile [k][col] fp16, padded
        } m[2];
        float stage[64][152];      // fp32 output staging (38.9 KB)
    } sm;

    int block_row = blockIdx.x * 64;
    int tid  = threadIdx.x;
    int wid  = tid >> 5;                 // 0..7
    int wr   = (wid >> 1) * 16;          // warp row offset
    int wc   = (wid & 1) * 64;           // warp col offset

    // per-thread load geometry (constant across tiles)
    int xrow0 = tid >> 2;                // i=0: f=tid    -> row=tid/8... recompute below
    (void)xrow0;

    wmma::fragment<wmma::accumulator, 16, 16, 16, float> acc[4];
    wmma::fragment<wmma::accumulator, 16, 16, 16, float> accS;
    #pragma unroll
    for (int c = 0; c < 4; c++) wmma::fill_fragment(acc[c], 0.f);
    wmma::fill_fragment(accS, 0.f);

    float4 xv[2];
    uint4  wv[3];
    // W-load predicate/geometry
    int wf[3], wk[3], wc8[3];
    #pragma unroll
    for (int i = 0; i < 3; i++) {
        wf[i] = i*256 + tid;
        wk[i] = wf[i] / 18;
        wc8[i] = (wf[i] - wk[i]*18) * 8;
    }
    int xrow[2], xkq[2];
    #pragma unroll
    for (int i = 0; i < 2; i++) {
        int f = i*256 + tid;
        xrow[i] = f >> 3;
        xkq[i]  = f & 7;
    }

    auto load_regs = [&](int kt) {
        #pragma unroll
        for (int i = 0; i < 2; i++)
            xv[i] = *(const float4*)(x + (size_t)(block_row+xrow[i])*INC + kt + xkq[i]*4);
        #pragma unroll
        for (int i = 0; i < 3; i++)
            if (wf[i] < 576)
                wv[i] = *(const uint4*)&d_Waug[(kt+wk[i])*NAUG + wc8[i]];
    };
    auto store_tile = [&](int buf) {
        #pragma unroll
        for (int i = 0; i < 2; i++) {
            __half2 h0 = __floats2half2_rn(xv[i].x, xv[i].y);
            __half2 h1 = __floats2half2_rn(xv[i].z, xv[i].w);
            uint2 u; u.x = *(unsigned*)&h0; u.y = *(unsigned*)&h1;
            *(uint2*)&sm.m[buf].xa[xrow[i]][xkq[i]*4] = u;
        }
        #pragma unroll
        for (int i = 0; i < 3; i++)
            if (wf[i] < 576)
                *(uint4*)&sm.m[buf].ws[wk[i]][wc8[i]] = wv[i];
    };

    load_regs(0);
    store_tile(0);
    __syncthreads();

    int buf = 0;
    #pragma unroll
    for (int t = 0; t < 8; t++) {           // 8 k-tiles of 32
        if (t < 7) load_regs((t+1)*32);     // prefetch next tile (in flight during MMA)

        #pragma unroll
        for (int ks = 0; ks < 32; ks += 16) {
            wmma::fragment<wmma::matrix_a, 16, 16, 16, __half, wmma::row_major> af;
            wmma::load_matrix_sync(af, &sm.m[buf].xa[wr][ks], 40);
            #pragma unroll
            for (int c = 0; c < 4; c++) {
                wmma::fragment<wmma::matrix_b, 16, 16, 16, __half, wmma::row_major> bf;
                wmma::load_matrix_sync(bf, &sm.m[buf].ws[ks][wc + c*16], 152);
                wmma::mma_sync(acc[c], af, bf, acc[c]);
            }
            if (wc == 0) {
                wmma::fragment<wmma::matrix_b, 16, 16, 16, __half, wmma::row_major> bf;
                wmma::load_matrix_sync(bf, &sm.m[buf].ws[ks][128], 152);
                wmma::mma_sync(accS, af, bf, accS);
            }
        }
        if (t < 7) {
            store_tile(buf ^ 1);
            __syncthreads();
            buf ^= 1;
        }
    }
    __syncthreads();   // all MMA reads done before stage overwrites the union

    // epilogue: stage fp32 results, then emit fp16 g (node-major) + scores
    #pragma unroll
    for (int c = 0; c < 4; c++)
        wmma::store_matrix_sync(&sm.stage[wr][wc + c*16], acc[c], 152, wmma::mem_row_major);
    if (wc == 0)
        wmma::store_matrix_sync(&sm.stage[wr][128], accS, 152, wmma::mem_row_major);
    __syncthreads();

    int tx = tid & 15;          // 8-col group
    int ty = tid >> 4;          // 0..15
    #pragma unroll
    for (int r = ty; r < 64; r += 16) {
        int row = block_row + r;
        int bb = row >> 11;
        int nn = row & (Nn-1);
        const float* st = &sm.stage[r][tx*8];
        __half2 h0 = __floats2half2_rn(st[0], st[1]);
        __half2 h1 = __floats2half2_rn(st[2], st[3]);
        __half2 h2 = __floats2half2_rn(st[4], st[5]);
        __half2 h3 = __floats2half2_rn(st[6], st[7]);
        uint4 u;
        u.x = *(unsigned*)&h0; u.y = *(unsigned*)&h1;
        u.z = *(unsigned*)&h2; u.w = *(unsigned*)&h3;
        *(uint4*)&d_g16[(size_t)(nn*8 + bb)*OUTC + tx*8] = u;   // node-major
    }

    if (tid < 128) {
        int srow = tid >> 1;             // 0..63
        int sq   = (tid & 1) * 4;        // 0 = src cols, 4 = dst cols
        const float* st = &sm.stage[srow][128 + sq];
        float4 sv = make_float4(st[0], st[1], st[2], st[3]);
        int grow = block_row + srow;
        int gb_ = grow >> 11;
        int gn  = grow & (Nn-1);
        if (sq == 0) d_ssrc[gn*8 + gb_] = sv;    // node-major
        else         d_sdst[gn*8 + gb_] = sv;
    }
}

__device__ __forceinline__ float edge_val(float4 ss, float4 sd) {
    float v0 = ss.x + sd.x, v1 = ss.y + sd.y, v2 = ss.z + sd.z, v3 = ss.w + sd.w;
    v0 = v0 > 0.f ? v0 : 0.2f*v0;
    v1 = v1 > 0.f ? v1 : 0.2f*v1;
    v2 = v2 > 0.f ? v2 : 0.2f*v2;
    v3 = v3 > 0.f ? v3 : 0.2f*v3;
    return 0.25f*(v0+v1+v2+v3);
}

// ---------------- agg: block/dst, warp/batch; f32x2 FMA, unroll 8 ------------
// No max subtraction: scores bounded, expf exact in fp32, softmax shift-invariant.
__global__ void __launch_bounds__(256) k_agg(float* __restrict__ out) {
    int d    = blockIdx.x;
    int b    = threadIdx.x >> 5;    // warp = batch
    int lane = threadIdx.x & 31;
    int cnt  = min(d_counts[d], CAPD);
    float4* o4 = (float4*)(out + ((size_t)b*Nn + d)*OUTC);

    if (cnt == 0) { o4[lane] = make_float4(0.f,0.f,0.f,0.f); return; }

    __shared__ int   scol[CAPD];
    __shared__ float sp[8][CAPD];
    __shared__ float sb[8][128];
    __shared__ float sb2[8][128];

    if (threadIdx.x < cnt) scol[threadIdx.x] = __ldg(&d_colp[d*CAPD + threadIdx.x]);
    __syncthreads();

    float4 sd = d_sdst[d*8 + b];                 // node-major
    float lsum = 0.f;
    unsigned long long acc01 = 0ULL, acc23 = 0ULL;
    const uint2* gb = (const uint2*)d_g16;       // row (n*8+b) = 32 uint2

    for (int jj = lane; jj < cnt; jj += 32) {
        int s = scol[jj];
        float p = __expf(edge_val(d_ssrc[s*8 + b], sd));
        sp[b][jj] = p;
        lsum += p;
    }
    __syncwarp();
    int jj = 0;
    for (; jj + 8 <= cnt; jj += 8) {
        uint2 u[8];
        float p[8];
        #pragma unroll
        for (int i = 0; i < 8; i++) {
            p[i] = sp[b][jj+i];
            u[i] = __ldg(gb + ((size_t)scol[jj+i]*8 + b)*32 + lane);
        }
        #pragma unroll
        for (int i = 0; i < 8; i++) {
            unsigned long long pd = pack2s(p[i], p[i]);
            float2 f0 = __half22float2(*(__half2*)&u[i].x);
            float2 f1 = __half22float2(*(__half2*)&u[i].y);
            acc01 = fma2(pd, pack2f(f0), acc01);
            acc23 = fma2(pd, pack2f(f1), acc23);
        }
    }
    for (; jj < cnt; jj++) {
        float p = sp[b][jj];
        uint2 u = __ldg(gb + ((size_t)scol[jj]*8 + b)*32 + lane);
        unsigned long long pd = pack2s(p, p);
        float2 f0 = __half22float2(*(__half2*)&u.x);
        float2 f1 = __half22float2(*(__half2*)&u.y);
        acc01 = fma2(pd, pack2f(f0), acc01);
        acc23 = fma2(pd, pack2f(f1), acc23);
    }
    #pragma unroll
    for (int off = 16; off; off >>= 1)
        lsum += __shfl_xor_sync(0xffffffff, lsum, off);
    float inv = 1.f / lsum;
    float2 c01 = unpack2(acc01);
    float2 c23 = unpack2(acc23);
    float a0 = c01.x*inv, a1 = c01.y*inv, a2 = c23.x*inv, a3 = c23.y*inv;
    o4[lane] = make_float4(a0, a1, a2, a3);

    // fused BN partials
    int c0 = lane*4;
    sb [b][c0+0]=a0;    sb [b][c0+1]=a1;    sb [b][c0+2]=a2;    sb [b][c0+3]=a3;
    sb2[b][c0+0]=a0*a0; sb2[b][c0+1]=a1*a1; sb2[b][c0+2]=a2*a2; sb2[b][c0+3]=a3*a3;
    __syncthreads();
    int t = threadIdx.x;
    if (t < 128) {
        float s = 0.f, s2 = 0.f;
        #pragma unroll
        for (int w = 0; w < 8; w++) { s += sb[w][t]; s2 += sb2[w][t]; }
        atomicAdd(&d_ssum[t], s);
        atomicAdd(&d_ssumsq[t], s2);
    }
}

// ---------------- BN apply + ELU (in place, float4, fast exp) ----------------
__global__ void k_final(float* __restrict__ out,
                        const float* __restrict__ gamma,
                        const float* __restrict__ beta) {
    int i = blockIdx.x*blockDim.x + threadIdx.x;     // float4 index
    if (i >= ROWS*OUTC/4) return;
    int c0 = (i*4) & (OUTC-1);
    const float inv = 1.f/(float)ROWS;
    float4 v = ((const float4*)out)[i];
    float r[4] = {v.x, v.y, v.z, v.w};
    #pragma unroll
    for (int j = 0; j < 4; j++) {
        int c = c0 + j;
        float mean = d_ssum[c]  * inv;
        float var  = d_ssumsq[c]* inv - mean*mean;
        float y = (r[j] - mean) * rsqrtf(var + BN_EPS) * __ldg(&gamma[c]) + __ldg(&beta[c]);
        r[j] = y > 0.f ? y : (__expf(y) - 1.f);
    }
    ((float4*)out)[i] = make_float4(r[0], r[1], r[2], r[3]);
}

// ---------------- launch: fork-join graph ------------------------------------
extern "C" void kernel_launch(void* const* d_in, const int* in_sizes, int n_in,
                              void* d_out, int out_size) {
    const float* x     = (const float*)d_in[0];
    const void*  ei    = d_in[1];
    const float* W     = (const float*)d_in[2];
    const float* a     = (const float*)d_in[3];
    const float* gamma = (const float*)d_in[4];
    const float* beta  = (const float*)d_in[5];
    float* out = (float*)d_out;

    static cudaStream_t s1 = nullptr;
    static cudaEvent_t  e0 = nullptr, e1 = nullptr;
    if (s1 == nullptr) {
        cudaStreamCreateWithFlags(&s1, cudaStreamNonBlocking);
        cudaEventCreateWithFlags(&e0, cudaEventDisableTiming);
        cudaEventCreateWithFlags(&e1, cudaEventDisableTiming);
    }

    // fork side stream at t=0; submit its kernels first
    cudaEventRecord(e0, 0);
    cudaStreamWaitEvent(s1, e0, 0);
    k_reset  <<<128, 256, 0, s1>>>((const unsigned*)ei);
    k_dedup  <<<EDG/512, 256, 0, s1>>>(ei);
    cudaEventRecord(e1, s1);

    // main stream: weights -> fused fp16 GEMM (+tensorized scores)
    k_weights<<<INC, 128>>>(W, a);
    k_gemm_g <<<ROWS/64, 256>>>(x);

    // join: aggregation (+BN stats) + BN/ELU
    cudaStreamWaitEvent(0, e1, 0);
    k_agg    <<<Nn, 256>>>(out);
    k_final  <<<(ROWS*OUTC/4 + 255)/256, 256>>>(out, gamma, beta);
}

// round 16
// speedup vs baseline: 1.3006x; 1.0878x over previous
#include <cuda_runtime.h>
#include <cuda_fp16.h>
#include <mma.h>
#include <math.h>

using namespace nvcuda;

#define Bz    8
#define Nn    2048
#define INC   256
#define OUTC  128
#define NAUG  144              // 128 g-cols + 8 score cols + 8 zero pad
#define EDG   65536
#define ROWS  (Bz*Nn)          // 16384
#define CAPD  128              // per-dst CSR capacity (Poisson(32): P(>128)~0)
#define BN_EPS 1e-5f

// ---------------- scratch (static device globals; no runtime alloc) --------
__device__ __half d_Waug[INC*NAUG];       // [Wg | Wsd | 0] fp16 [256][144]
__device__ __half d_g16[ROWS*OUTC];       // g, NODE-MAJOR: [n][b][c] fp16 (4 MB)
__device__ float4 d_ssrc[ROWS];           // NODE-MAJOR: [n][b]
__device__ float4 d_sdst[ROWS];           // NODE-MAJOR: [n][b]
__device__ unsigned d_bitmap[(Nn*Nn)/32]; // 512 KB dedup bitmap
__device__ int d_counts[Nn];              // per-dst degree (append cursor)
__device__ int d_colp[Nn*CAPD];           // padded CSR: [dst][CAPD]
__device__ float d_ssum[OUTC];
__device__ float d_ssumsq[OUTC];
__device__ int d_is64;

// ---------------- f32x2 packed helpers (Blackwell) ---------------------------
__device__ __forceinline__ unsigned long long pack2f(float2 v) {
    unsigned long long r;
    asm("mov.b64 %0, {%1, %2};" : "=l"(r) : "f"(v.x), "f"(v.y));
    return r;
}
__device__ __forceinline__ unsigned long long pack2s(float lo, float hi) {
    unsigned long long r;
    asm("mov.b64 %0, {%1, %2};" : "=l"(r) : "f"(lo), "f"(hi));
    return r;
}
__device__ __forceinline__ unsigned long long fma2(unsigned long long a,
                                                   unsigned long long b,
                                                   unsigned long long c) {
    unsigned long long d;
    asm("fma.rn.f32x2 %0, %1, %2, %3;" : "=l"(d) : "l"(a), "l"(b), "l"(c));
    return d;
}
__device__ __forceinline__ float2 unpack2(unsigned long long v) {
    float lo, hi;
    asm("mov.b64 {%0, %1}, %2;" : "=f"(lo), "=f"(hi) : "l"(v));
    return make_float2(lo, hi);
}

// ---------------- prep: bitmap/count reset + dtype sniff + weight fold -------
// grid 384 x 256: blocks 0..127 reset; blocks 128..383 fold W,a into Waug.
__global__ void k_prep(const unsigned* __restrict__ ei32,
                       const float* __restrict__ W,
                       const float* __restrict__ a) {
    __shared__ float part[4][8];
    int bid = blockIdx.x, tid = threadIdx.x;
    if (bid < 128) {
        int i = bid*256 + tid;                           // 0..32767
        ((uint4*)d_bitmap)[i] = make_uint4(0u,0u,0u,0u); // 512 KB
        if (i < Nn)  d_counts[i] = 0;
        if (i < OUTC){ d_ssum[i] = 0.f; d_ssumsq[i] = 0.f; }
        if (i == 0) {
            int is64 = 1;
            #pragma unroll 1
            for (int t = 1; t < 128; t += 2)
                if (ei32[t] != 0u) { is64 = 0; break; }
            d_is64 = is64;
        }
    } else {
        int k    = bid - 128;        // 0..255
        int c    = tid & 127;
        int grp  = tid >> 7;         // 0: src (j 0..3), 1: dst (j 4..7)
        int lane = tid & 31;
        int cw   = c >> 5;           // c-warp 0..3
        float w0 = W[k*512 +       c];
        float w1 = W[k*512 + 128 + c];
        float w2 = W[k*512 + 256 + c];
        float w3 = W[k*512 + 384 + c];
        if (grp == 0) d_Waug[k*NAUG + c] = __float2half(0.25f*(w0+w1+w2+w3));
        float av = (grp == 0) ? a[c] : a[128+c];
        float vals[4] = {w0*av, w1*av, w2*av, w3*av};
        #pragma unroll
        for (int jj = 0; jj < 4; jj++) {
            float v = vals[jj];
            #pragma unroll
            for (int off = 16; off; off >>= 1) v += __shfl_xor_sync(0xffffffff, v, off);
            if (lane == 0) part[cw][grp*4 + jj] = v;
        }
        __syncthreads();
        if (tid < 8)
            d_Waug[k*NAUG + 128 + tid] =
                __float2half(part[0][tid] + part[1][tid] + part[2][tid] + part[3][tid]);
        else if (tid < 16)
            d_Waug[k*NAUG + 128 + tid] = __float2half(0.f);
    }
}

__device__ __forceinline__ int edge_at(const void* ei, int idx) {
    if (d_is64) return (int)((const long long*)ei)[idx];
    return ((const int*)ei)[idx];
}

// ---------------- dedup + direct padded-CSR append (2 edges/thread) ----------
__global__ void k_dedup(const void* __restrict__ ei) {
    int e0 = (blockIdx.x*blockDim.x + threadIdx.x) * 2;
    if (e0 >= EDG) return;
    int s0 = edge_at(ei, e0),     s1 = edge_at(ei, e0+1);
    int d0 = edge_at(ei, EDG+e0), d1 = edge_at(ei, EDG+e0+1);
    int ss[2] = {s0, s1};
    int dd[2] = {d0, d1};
    #pragma unroll
    for (int i = 0; i < 2; i++) {
        unsigned key = (unsigned)dd[i]*(unsigned)Nn + (unsigned)ss[i];
        unsigned mask = 1u << (key & 31);
        unsigned old = atomicOr(&d_bitmap[key >> 5], mask);
        if (!(old & mask)) {
            int pos = atomicAdd(&d_counts[dd[i]], 1);
            if (pos < CAPD) d_colp[dd[i]*CAPD + pos] = ss[i];
        }
    }
}

// ---------------- fused GEMM: [g | scores] = x @ Waug, double-buffered -------
__global__ void __launch_bounds__(256) k_gemm_g(const float* __restrict__ x) {
    __shared__ union SM {
        struct {
            __half xa[64][40];
            __half ws[32][152];
        } m[2];
        float stage[64][152];
    } sm;

    int block_row = blockIdx.x * 64;
    int tid  = threadIdx.x;
    int wid  = tid >> 5;
    int wr   = (wid >> 1) * 16;
    int wc   = (wid & 1) * 64;

    wmma::fragment<wmma::accumulator, 16, 16, 16, float> acc[4];
    wmma::fragment<wmma::accumulator, 16, 16, 16, float> accS;
    #pragma unroll
    for (int c = 0; c < 4; c++) wmma::fill_fragment(acc[c], 0.f);
    wmma::fill_fragment(accS, 0.f);

    float4 xv[2];
    uint4  wv[3];
    int wf[3], wk[3], wc8[3];
    #pragma unroll
    for (int i = 0; i < 3; i++) {
        wf[i] = i*256 + tid;
        wk[i] = wf[i] / 18;
        wc8[i] = (wf[i] - wk[i]*18) * 8;
    }
    int xrow[2], xkq[2];
    #pragma unroll
    for (int i = 0; i < 2; i++) {
        int f = i*256 + tid;
        xrow[i] = f >> 3;
        xkq[i]  = f & 7;
    }

    auto load_regs = [&](int kt) {
        #pragma unroll
        for (int i = 0; i < 2; i++)
            xv[i] = *(const float4*)(x + (size_t)(block_row+xrow[i])*INC + kt + xkq[i]*4);
        #pragma unroll
        for (int i = 0; i < 3; i++)
            if (wf[i] < 576)
                wv[i] = *(const uint4*)&d_Waug[(kt+wk[i])*NAUG + wc8[i]];
    };
    auto store_tile = [&](int buf) {
        #pragma unroll
        for (int i = 0; i < 2; i++) {
            __half2 h0 = __floats2half2_rn(xv[i].x, xv[i].y);
            __half2 h1 = __floats2half2_rn(xv[i].z, xv[i].w);
            uint2 u; u.x = *(unsigned*)&h0; u.y = *(unsigned*)&h1;
            *(uint2*)&sm.m[buf].xa[xrow[i]][xkq[i]*4] = u;
        }
        #pragma unroll
        for (int i = 0; i < 3; i++)
            if (wf[i] < 576)
                *(uint4*)&sm.m[buf].ws[wk[i]][wc8[i]] = wv[i];
    };

    load_regs(0);
    store_tile(0);
    __syncthreads();

    int buf = 0;
    #pragma unroll
    for (int t = 0; t < 8; t++) {
        if (t < 7) load_regs((t+1)*32);

        #pragma unroll
        for (int ks = 0; ks < 32; ks += 16) {
            wmma::fragment<wmma::matrix_a, 16, 16, 16, __half, wmma::row_major> af;
            wmma::load_matrix_sync(af, &sm.m[buf].xa[wr][ks], 40);
            #pragma unroll
            for (int c = 0; c < 4; c++) {
                wmma::fragment<wmma::matrix_b, 16, 16, 16, __half, wmma::row_major> bf;
                wmma::load_matrix_sync(bf, &sm.m[buf].ws[ks][wc + c*16], 152);
                wmma::mma_sync(acc[c], af, bf, acc[c]);
            }
            if (wc == 0) {
                wmma::fragment<wmma::matrix_b, 16, 16, 16, __half, wmma::row_major> bf;
                wmma::load_matrix_sync(bf, &sm.m[buf].ws[ks][128], 152);
                wmma::mma_sync(accS, af, bf, accS);
            }
        }
        if (t < 7) {
            store_tile(buf ^ 1);
            __syncthreads();
            buf ^= 1;
        }
    }
    __syncthreads();

    #pragma unroll
    for (int c = 0; c < 4; c++)
        wmma::store_matrix_sync(&sm.stage[wr][wc + c*16], acc[c], 152, wmma::mem_row_major);
    if (wc == 0)
        wmma::store_matrix_sync(&sm.stage[wr][128], accS, 152, wmma::mem_row_major);
    __syncthreads();

    int tx = tid & 15;
    int ty = tid >> 4;
    #pragma unroll
    for (int r = ty; r < 64; r += 16) {
        int row = block_row + r;
        int bb = row >> 11;
        int nn = row & (Nn-1);
        const float* st = &sm.stage[r][tx*8];
        __half2 h0 = __floats2half2_rn(st[0], st[1]);
        __half2 h1 = __floats2half2_rn(st[2], st[3]);
        __half2 h2 = __floats2half2_rn(st[4], st[5]);
        __half2 h3 = __floats2half2_rn(st[6], st[7]);
        uint4 u;
        u.x = *(unsigned*)&h0; u.y = *(unsigned*)&h1;
        u.z = *(unsigned*)&h2; u.w = *(unsigned*)&h3;
        *(uint4*)&d_g16[(size_t)(nn*8 + bb)*OUTC + tx*8] = u;   // node-major
    }

    if (tid < 128) {
        int srow = tid >> 1;
        int sq   = (tid & 1) * 4;
        const float* st = &sm.stage[srow][128 + sq];
        float4 sv = make_float4(st[0], st[1], st[2], st[3]);
        int grow = block_row + srow;
        int gb_ = grow >> 11;
        int gn  = grow & (Nn-1);
        if (sq == 0) d_ssrc[gn*8 + gb_] = sv;
        else         d_sdst[gn*8 + gb_] = sv;
    }
}

__device__ __forceinline__ float edge_val(float4 ss, float4 sd) {
    float v0 = ss.x + sd.x, v1 = ss.y + sd.y, v2 = ss.z + sd.z, v3 = ss.w + sd.w;
    v0 = v0 > 0.f ? v0 : 0.2f*v0;
    v1 = v1 > 0.f ? v1 : 0.2f*v1;
    v2 = v2 > 0.f ? v2 : 0.2f*v2;
    v3 = v3 > 0.f ? v3 : 0.2f*v3;
    return 0.25f*(v0+v1+v2+v3);
}

// ---------------- agg: 2 dst per block (single balanced wave), warp/batch ----
// Gather: 16B/lane, half-warps own edge parities, shfl-combine at the end.
// No max subtraction: scores bounded, expf exact in fp32, softmax shift-invariant.
__global__ void __launch_bounds__(256) k_agg(float* __restrict__ out) {
    int tid  = threadIdx.x;
    int b    = tid >> 5;            // warp = batch
    int lane = tid & 31;
    int lp   = lane >> 4;           // edge parity (0/1)
    int c16  = lane & 15;           // 16-byte channel group (8 halves)

    __shared__ int   scol[CAPD];
    __shared__ float sp[8][CAPD];
    __shared__ float sb[8][128];
    __shared__ float sb2[8][128];

    float bnsum[8], bnsq[8];
    #pragma unroll
    for (int q = 0; q < 8; q++) { bnsum[q] = 0.f; bnsq[q] = 0.f; }

    const uint4* gb16 = (const uint4*)d_g16;   // row (n*8+b) = 16 uint4

    #pragma unroll 1
    for (int it = 0; it < 2; it++) {
        int d   = blockIdx.x*2 + it;
        int cnt = min(d_counts[d], CAPD);
        float4* o4 = (float4*)(out + ((size_t)b*Nn + d)*OUTC);

        __syncthreads();                         // protect scol/sp reuse
        if (tid < cnt) scol[tid] = __ldg(&d_colp[d*CAPD + tid]);
        __syncthreads();

        if (cnt == 0) { o4[lane] = make_float4(0.f,0.f,0.f,0.f); continue; }

        float4 sd = d_sdst[d*8 + b];
        float lsum = 0.f;
        for (int jj = lane; jj < cnt; jj += 32) {
            int s = scol[jj];
            float p = __expf(edge_val(d_ssrc[s*8 + b], sd));
            sp[b][jj] = p;
            lsum += p;
        }
        __syncwarp();

        unsigned long long a01 = 0ULL, a23 = 0ULL, a45 = 0ULL, a67 = 0ULL;
        int jj = lp;
        for (; jj + 6 < cnt; jj += 8) {          // 4 edges per lane per iter
            uint4 u[4];
            float p[4];
            #pragma unroll
            for (int i = 0; i < 4; i++) {
                int e = jj + 2*i;
                p[i] = sp[b][e];
                u[i] = __ldg(gb16 + (size_t)(scol[e]*8 + b)*16 + c16);
            }
            #pragma unroll
            for (int i = 0; i < 4; i++) {
                unsigned long long pd = pack2s(p[i], p[i]);
                float2 f0 = __half22float2(*(__half2*)&u[i].x);
                float2 f1 = __half22float2(*(__half2*)&u[i].y);
                float2 f2 = __half22float2(*(__half2*)&u[i].z);
                float2 f3 = __half22float2(*(__half2*)&u[i].w);
                a01 = fma2(pd, pack2f(f0), a01);
                a23 = fma2(pd, pack2f(f1), a23);
                a45 = fma2(pd, pack2f(f2), a45);
                a67 = fma2(pd, pack2f(f3), a67);
            }
        }
        for (; jj < cnt; jj += 2) {
            float p = sp[b][jj];
            uint4 u = __ldg(gb16 + (size_t)(scol[jj]*8 + b)*16 + c16);
            unsigned long long pd = pack2s(p, p);
            float2 f0 = __half22float2(*(__half2*)&u.x);
            float2 f1 = __half22float2(*(__half2*)&u.y);
            float2 f2 = __half22float2(*(__half2*)&u.z);
            float2 f3 = __half22float2(*(__half2*)&u.w);
            a01 = fma2(pd, pack2f(f0), a01);
            a23 = fma2(pd, pack2f(f1), a23);
            a45 = fma2(pd, pack2f(f2), a45);
            a67 = fma2(pd, pack2f(f3), a67);
        }

        #pragma unroll
        for (int off = 16; off; off >>= 1)
            lsum += __shfl_xor_sync(0xffffffff, lsum, off);
        float inv = 1.f / lsum;

        float2 c01 = unpack2(a01), c23 = unpack2(a23);
        float2 c45 = unpack2(a45), c67 = unpack2(a67);
        float v[8] = {c01.x,c01.y,c23.x,c23.y,c45.x,c45.y,c67.x,c67.y};
        #pragma unroll
        for (int q = 0; q < 8; q++) {
            v[q] += __shfl_xor_sync(0xffffffff, v[q], 16);   // combine edge parities
            v[q] *= inv;
        }
        if (lp == 0) {
            o4[c16*2]   = make_float4(v[0], v[1], v[2], v[3]);
            o4[c16*2+1] = make_float4(v[4], v[5], v[6], v[7]);
            #pragma unroll
            for (int q = 0; q < 8; q++) { bnsum[q] += v[q]; bnsq[q] += v[q]*v[q]; }
        }
    }

    // BN tail (once): lane<16 holds channels c16*8..+7
    if (lp == 0) {
        #pragma unroll
        for (int q = 0; q < 8; q++) {
            sb [b][c16*8 + q] = bnsum[q];
            sb2[b][c16*8 + q] = bnsq[q];
        }
    }
    __syncthreads();
    if (tid < 128) {
        float s = 0.f, s2 = 0.f;
        #pragma unroll
        for (int w = 0; w < 8; w++) { s += sb[w][tid]; s2 += sb2[w][tid]; }
        atomicAdd(&d_ssum[tid], s);
        atomicAdd(&d_ssumsq[tid], s2);
    }
}

// ---------------- BN apply + ELU (in place, float4, fast exp) ----------------
__global__ void k_final(float* __restrict__ out,
                        const float* __restrict__ gamma,
                        const float* __restrict__ beta) {
    int i = blockIdx.x*blockDim.x + threadIdx.x;     // float4 index
    if (i >= ROWS*OUTC/4) return;
    int c0 = (i*4) & (OUTC-1);
    const float inv = 1.f/(float)ROWS;
    float4 v = ((const float4*)out)[i];
    float r[4] = {v.x, v.y, v.z, v.w};
    #pragma unroll
    for (int j = 0; j < 4; j++) {
        int c = c0 + j;
        float mean = d_ssum[c]  * inv;
        float var  = d_ssumsq[c]* inv - mean*mean;
        float y = (r[j] - mean) * rsqrtf(var + BN_EPS) * __ldg(&gamma[c]) + __ldg(&beta[c]);
        r[j] = y > 0.f ? y : (__expf(y) - 1.f);
    }
    ((float4*)out)[i] = make_float4(r[0], r[1], r[2], r[3]);
}

// ---------------- launch: fork-join graph (agg is 4th-submitted) -------------
extern "C" void kernel_launch(void* const* d_in, const int* in_sizes, int n_in,
                              void* d_out, int out_size) {
    const float* x     = (const float*)d_in[0];
    const void*  ei    = d_in[1];
    const float* W     = (const float*)d_in[2];
    const float* a     = (const float*)d_in[3];
    const float* gamma = (const float*)d_in[4];
    const float* beta  = (const float*)d_in[5];
    float* out = (float*)d_out;

    static cudaStream_t s1 = nullptr;
    static cudaEvent_t  e0 = nullptr, e1 = nullptr;
    if (s1 == nullptr) {
        cudaStreamCreateWithFlags(&s1, cudaStreamNonBlocking);
        cudaEventCreateWithFlags(&e0, cudaEventDisableTiming);
        cudaEventCreateWithFlags(&e1, cudaEventDisableTiming);
    }

    // main: prep (reset + weights)
    k_prep<<<384, 256>>>((const unsigned*)ei, W, a);
    cudaEventRecord(e0, 0);

    // side: dedup (needs prep's bitmap clear)
    cudaStreamWaitEvent(s1, e0, 0);
    k_dedup<<<EDG/512, 256, 0, s1>>>(ei);
    cudaEventRecord(e1, s1);

    // main: fused fp16 GEMM (+tensorized scores), concurrent with dedup
    k_gemm_g<<<ROWS/64, 256>>>(x);

    // join: aggregation (+BN stats) + BN/ELU
    cudaStreamWaitEvent(0, e1, 0);
    k_agg  <<<Nn/2, 256>>>(out);
    k_final<<<(ROWS*OUTC/4 + 255)/256, 256>>>(out, gamma, beta);
}